// round 4
// baseline (speedup 1.0000x reference)
#include <cuda_runtime.h>
#include <cstdint>

// Problem constants
#define BB   4
#define RR   64
#define CC   64
#define DD   512
#define HH   4
#define DHH  128
#define SS   4096              // R*C
#define MTOT (BB*SS)           // 16384
#define NEGV (-1e6f)

// ---------------- scratch (module-load allocated; no runtime allocs) ----------------
__device__ __align__(256) float g_q[(size_t)MTOT * DD];
__device__ __align__(256) float g_k[(size_t)MTOT * DD];
__device__ __align__(256) float g_v[(size_t)MTOT * DD];
__device__ __align__(256) float g_o[(size_t)MTOT * DD];

// =====================================================================
// SGEMM core: C[M,N] = A[M,K] * B[K,N] (row-major), 128x128 tile, BK=8,
// 256 threads, 8x8 per thread.  M=16384, N=512, K=512 here.
// =====================================================================
__device__ __forceinline__ void sgemm_128x128(
    const float* __restrict__ A, const float* __restrict__ B,
    float* __restrict__ C, float scale)
{
    __shared__ float As[8][128];   // transposed: As[k][m]
    __shared__ float Bs[8][128];

    const int tid = threadIdx.x;
    const int tx  = tid & 15;
    const int ty  = tid >> 4;
    const int rowBase = blockIdx.y * 128;
    const int colBase = blockIdx.x * 128;

    const int arow = tid >> 1;         // 0..127
    const int acol = (tid & 1) * 4;    // 0 or 4
    const int brow = tid >> 5;         // 0..7
    const int bcol = (tid & 31) * 4;   // 0..124

    float acc[8][8];
#pragma unroll
    for (int i = 0; i < 8; i++)
#pragma unroll
        for (int j = 0; j < 8; j++) acc[i][j] = 0.f;

    const int K = DD, N = DD;
    for (int k0 = 0; k0 < K; k0 += 8) {
        float4 av = *(const float4*)(A + (size_t)(rowBase + arow) * K + k0 + acol);
        float4 bv = *(const float4*)(B + (size_t)(k0 + brow) * N + colBase + bcol);
        As[acol + 0][arow] = av.x;
        As[acol + 1][arow] = av.y;
        As[acol + 2][arow] = av.z;
        As[acol + 3][arow] = av.w;
        *(float4*)(&Bs[brow][bcol]) = bv;
        __syncthreads();
#pragma unroll
        for (int kk = 0; kk < 8; kk++) {
            float a[8], b[8];
            *(float4*)(a)     = *(const float4*)(&As[kk][ty * 8]);
            *(float4*)(a + 4) = *(const float4*)(&As[kk][ty * 8 + 4]);
            *(float4*)(b)     = *(const float4*)(&Bs[kk][tx * 8]);
            *(float4*)(b + 4) = *(const float4*)(&Bs[kk][tx * 8 + 4]);
#pragma unroll
            for (int i = 0; i < 8; i++)
#pragma unroll
                for (int j = 0; j < 8; j++)
                    acc[i][j] += a[i] * b[j];
        }
        __syncthreads();
    }

#pragma unroll
    for (int i = 0; i < 8; i++) {
        float4 o0, o1;
        o0.x = acc[i][0] * scale; o0.y = acc[i][1] * scale;
        o0.z = acc[i][2] * scale; o0.w = acc[i][3] * scale;
        o1.x = acc[i][4] * scale; o1.y = acc[i][5] * scale;
        o1.z = acc[i][6] * scale; o1.w = acc[i][7] * scale;
        float* cp = C + (size_t)(rowBase + ty * 8 + i) * N + colBase + tx * 8;
        *(float4*)(cp)     = o0;
        *(float4*)(cp + 4) = o1;
    }
}

__global__ __launch_bounds__(256) void sgemm_proj(
    const float* __restrict__ x, const float* __restrict__ w, int which, float scale)
{
    float* C = (which == 0) ? g_q : (which == 1) ? g_k : g_v;
    sgemm_128x128(x, w, C, scale);
}

__global__ __launch_bounds__(256) void sgemm_out(
    const float* __restrict__ wo, float* __restrict__ out)
{
    sgemm_128x128(g_o, wo, out, 1.0f);
}

// =====================================================================
// Flash attention, causal (raster order), factorized relative bias.
// Tile: 64 queries x 64 keys, DH=128.  256 threads, 1 CTA / (q-tile, b*h).
// =====================================================================
#define PPAD 68
#define VPAD 132
#define ATT_SMEM_FLOATS (128*64 + 128*64 + 64*VPAD + 64*PPAD + 64*3 + 256*2 + 128*2)
#define ATT_SMEM_BYTES  (ATT_SMEM_FLOATS * 4)

__global__ __launch_bounds__(256, 1) void attn_kernel(
    const float* __restrict__ rel_row, const float* __restrict__ rel_col)
{
    extern __shared__ float smf[];
    float* Qt   = smf;               // [128][64] (e-major, transposed)
    float* Kt   = Qt + 128 * 64;     // [128][64]
    float* Vs   = Kt + 128 * 64;     // [64][VPAD]
    float* Ps   = Vs + 64 * VPAD;    // [64][PPAD]
    float* mrow = Ps + 64 * PPAD;    // [64]
    float* lrow = mrow + 64;         // [64]
    float* alph = lrow + 64;         // [64]
    float* redm = alph + 64;         // [4][64]
    float* reds = redm + 256;        // [4][64]
    float* rr   = reds + 256;        // [128]
    float* rc   = rr + 128;          // [128]

    const int tid = threadIdx.x;
    const int qt  = 63 - blockIdx.x;      // largest-first for load balance
    const int bh  = blockIdx.y;
    const int b   = bh >> 2;
    const int h   = bh & 3;

    const float* Qg = g_q + (size_t)b * SS * DD + h * DHH;
    const float* Kg = g_k + (size_t)b * SS * DD + h * DHH;
    const float* Vg = g_v + (size_t)b * SS * DD + h * DHH;
    float*       Og = g_o + (size_t)b * SS * DD + h * DHH;

    if (tid < 128) {
        rr[tid] = rel_row[h * 128 + tid];
        rc[tid] = rel_col[h * 128 + tid];
    }
    if (tid < 64) { mrow[tid] = -1e30f; lrow[tid] = 0.f; }

    // load Q tile transposed: Qt[e][i]
    {
        const int q0 = qt * 64;
#pragma unroll
        for (int it = 0; it < 8; it++) {
            int f = tid + it * 256;          // 0..2047 float4s
            int srow = f >> 5;               // 0..63
            int e4 = (f & 31) << 2;          // 0..124
            float4 v = *(const float4*)(Qg + (size_t)(q0 + srow) * DD + e4);
            Qt[(e4 + 0) * 64 + srow] = v.x;
            Qt[(e4 + 1) * 64 + srow] = v.y;
            Qt[(e4 + 2) * 64 + srow] = v.z;
            Qt[(e4 + 3) * 64 + srow] = v.w;
        }
    }

    const int tx = tid & 15;
    const int ty = tid >> 4;
    float acc[4][8];
#pragma unroll
    for (int i = 0; i < 4; i++)
#pragma unroll
        for (int j = 0; j < 8; j++) acc[i][j] = 0.f;

    for (int kt = 0; kt <= qt; kt++) {
        __syncthreads();   // guards Qt/Kt/Vs/Ps reuse (and initial loads)
        const int k0 = kt * 64;
        // load K (transposed) and V tiles
#pragma unroll
        for (int it = 0; it < 8; it++) {
            int f = tid + it * 256;
            int srow = f >> 5;
            int e4 = (f & 31) << 2;
            float4 kv = *(const float4*)(Kg + (size_t)(k0 + srow) * DD + e4);
            Kt[(e4 + 0) * 64 + srow] = kv.x;
            Kt[(e4 + 1) * 64 + srow] = kv.y;
            Kt[(e4 + 2) * 64 + srow] = kv.z;
            Kt[(e4 + 3) * 64 + srow] = kv.w;
            float4 vv = *(const float4*)(Vg + (size_t)(k0 + srow) * DD + e4);
            *(float4*)(Vs + srow * VPAD + e4) = vv;
        }
        __syncthreads();

        // ---- S = Q K^T (4x4 per thread over 64x64 tile) ----
        float sacc[4][4];
#pragma unroll
        for (int i = 0; i < 4; i++)
#pragma unroll
            for (int j = 0; j < 4; j++) sacc[i][j] = 0.f;
#pragma unroll 8
        for (int e = 0; e < 128; e++) {
            float a[4], bb[4];
            *(float4*)a  = *(const float4*)(Qt + e * 64 + ty * 4);
            *(float4*)bb = *(const float4*)(Kt + e * 64 + tx * 4);
#pragma unroll
            for (int i = 0; i < 4; i++)
#pragma unroll
                for (int j = 0; j < 4; j++)
                    sacc[i][j] += a[i] * bb[j];
        }
        // bias + causal mask, write to Ps
        {
            const int i0 = ty * 4, j0 = tx * 4;
#pragma unroll
            for (int di = 0; di < 4; di++) {
                int qi = qt * 64 + i0 + di;
                int qr = qi >> 6, qc = qi & 63;
#pragma unroll
                for (int dj = 0; dj < 4; dj++) {
                    int kj = k0 + j0 + dj;
                    float bias = rr[63 + (kj >> 6) - qr] + rc[63 + (kj & 63) - qc];
                    float sv = sacc[di][dj] + bias;
                    if (kj > qi) sv += NEGV;
                    Ps[(i0 + di) * PPAD + j0 + dj] = sv;
                }
            }
        }
        __syncthreads();

        // ---- online softmax (4 partial lanes per row) ----
        {
            const int i = tid & 63;
            const int part = tid >> 6;
            const int jb = part << 4;
            float lm = -1e30f;
#pragma unroll
            for (int jj = 0; jj < 16; jj++)
                lm = fmaxf(lm, Ps[i * PPAD + jb + jj]);
            redm[part * 64 + i] = lm;
            __syncthreads();
            float mold = mrow[i];
            float mnew = fmaxf(mold,
                         fmaxf(fmaxf(redm[i], redm[64 + i]),
                               fmaxf(redm[128 + i], redm[192 + i])));
            float ls = 0.f;
#pragma unroll
            for (int jj = 0; jj < 16; jj++) {
                float p = __expf(Ps[i * PPAD + jb + jj] - mnew);
                Ps[i * PPAD + jb + jj] = p;
                ls += p;
            }
            reds[part * 64 + i] = ls;
            __syncthreads();
            if (part == 0) {
                float al = __expf(mold - mnew);
                lrow[i] = lrow[i] * al +
                          (reds[i] + reds[64 + i]) + (reds[128 + i] + reds[192 + i]);
                mrow[i] = mnew;
                alph[i] = al;
            }
            __syncthreads();
        }

        // ---- O = O*alpha + P V  (rows ty*4.., cols tx*8..) ----
        {
            float al[4];
#pragma unroll
            for (int dr = 0; dr < 4; dr++) al[dr] = alph[ty * 4 + dr];
#pragma unroll
            for (int dr = 0; dr < 4; dr++)
#pragma unroll
                for (int dc = 0; dc < 8; dc++) acc[dr][dc] *= al[dr];
#pragma unroll 2
            for (int j = 0; j < 64; j++) {
                float a0 = Ps[(ty * 4 + 0) * PPAD + j];
                float a1 = Ps[(ty * 4 + 1) * PPAD + j];
                float a2 = Ps[(ty * 4 + 2) * PPAD + j];
                float a3 = Ps[(ty * 4 + 3) * PPAD + j];
                float bb[8];
                *(float4*)(bb)     = *(const float4*)(Vs + j * VPAD + tx * 8);
                *(float4*)(bb + 4) = *(const float4*)(Vs + j * VPAD + tx * 8 + 4);
#pragma unroll
                for (int dc = 0; dc < 8; dc++) {
                    acc[0][dc] += a0 * bb[dc];
                    acc[1][dc] += a1 * bb[dc];
                    acc[2][dc] += a2 * bb[dc];
                    acc[3][dc] += a3 * bb[dc];
                }
            }
        }
    }

    // ---- normalize + write O ----
    {
        const int q0 = qt * 64;
#pragma unroll
        for (int dr = 0; dr < 4; dr++) {
            float linv = 1.0f / lrow[ty * 4 + dr];
            int srow = q0 + ty * 4 + dr;
            float4 o0, o1;
            o0.x = acc[dr][0] * linv; o0.y = acc[dr][1] * linv;
            o0.z = acc[dr][2] * linv; o0.w = acc[dr][3] * linv;
            o1.x = acc[dr][4] * linv; o1.y = acc[dr][5] * linv;
            o1.z = acc[dr][6] * linv; o1.w = acc[dr][7] * linv;
            float* op = Og + (size_t)srow * DD + tx * 8;
            *(float4*)(op)     = o0;
            *(float4*)(op + 4) = o1;
        }
    }
}

// =====================================================================
extern "C" void kernel_launch(void* const* d_in, const int* in_sizes, int n_in,
                              void* d_out, int out_size)
{
    const float* x       = (const float*)d_in[0];
    const float* wq      = (const float*)d_in[1];
    const float* wk      = (const float*)d_in[2];
    const float* wv      = (const float*)d_in[3];
    const float* wo      = (const float*)d_in[4];
    const float* rel_row = (const float*)d_in[5];
    const float* rel_col = (const float*)d_in[6];
    float* out = (float*)d_out;

    cudaFuncSetAttribute(attn_kernel,
                         cudaFuncAttributeMaxDynamicSharedMemorySize, ATT_SMEM_BYTES);

    dim3 gProj(DD / 128, MTOT / 128);   // (4, 128)
    const float qscale = 0.08838834764831845f;   // DH^-0.5

    sgemm_proj<<<gProj, 256>>>(x, wq, 0, qscale);
    sgemm_proj<<<gProj, 256>>>(x, wk, 1, 1.0f);
    sgemm_proj<<<gProj, 256>>>(x, wv, 2, 1.0f);

    attn_kernel<<<dim3(64, BB * HH), 256, ATT_SMEM_BYTES>>>(rel_row, rel_col);

    sgemm_out<<<gProj, 256>>>(wo, out);
}

// round 6
// speedup vs baseline: 1.0009x; 1.0009x over previous
#include <cuda_runtime.h>
#include <cstdint>

// Problem constants
#define BB   4
#define RR   64
#define CC   64
#define DD   512
#define HH   4
#define DHH  128
#define SS   4096              // R*C
#define MTOT (BB*SS)           // 16384
#define NEGV (-1e6f)

// ---------------- scratch (module-load allocated; no runtime allocs) ----------------
__device__ __align__(256) float g_q[(size_t)MTOT * DD];
__device__ __align__(256) float g_k[(size_t)MTOT * DD];
__device__ __align__(256) float g_v[(size_t)MTOT * DD];
__device__ __align__(256) float g_o[(size_t)MTOT * DD];

// =====================================================================
// SGEMM core: C[M,N] = A[M,K] * B[K,N] (row-major), 128x128 tile, BK=8,
// 256 threads, 8x8 per thread.  M=16384, N=512, K=512 here.
// =====================================================================
__device__ __forceinline__ void sgemm_128x128(
    const float* __restrict__ A, const float* __restrict__ B,
    float* __restrict__ C, float scale)
{
    __shared__ float As[8][128];   // transposed: As[k][m]
    __shared__ float Bs[8][128];

    const int tid = threadIdx.x;
    const int tx  = tid & 15;
    const int ty  = tid >> 4;
    const int rowBase = blockIdx.y * 128;
    const int colBase = blockIdx.x * 128;

    const int arow = tid >> 1;         // 0..127
    const int acol = (tid & 1) * 4;    // 0 or 4
    const int brow = tid >> 5;         // 0..7
    const int bcol = (tid & 31) * 4;   // 0..124

    float acc[8][8];
#pragma unroll
    for (int i = 0; i < 8; i++)
#pragma unroll
        for (int j = 0; j < 8; j++) acc[i][j] = 0.f;

    const int K = DD, N = DD;
    for (int k0 = 0; k0 < K; k0 += 8) {
        float4 av = *(const float4*)(A + (size_t)(rowBase + arow) * K + k0 + acol);
        float4 bv = *(const float4*)(B + (size_t)(k0 + brow) * N + colBase + bcol);
        As[acol + 0][arow] = av.x;
        As[acol + 1][arow] = av.y;
        As[acol + 2][arow] = av.z;
        As[acol + 3][arow] = av.w;
        *(float4*)(&Bs[brow][bcol]) = bv;
        __syncthreads();
#pragma unroll
        for (int kk = 0; kk < 8; kk++) {
            float a[8], b[8];
            *(float4*)(a)     = *(const float4*)(&As[kk][ty * 8]);
            *(float4*)(a + 4) = *(const float4*)(&As[kk][ty * 8 + 4]);
            *(float4*)(b)     = *(const float4*)(&Bs[kk][tx * 8]);
            *(float4*)(b + 4) = *(const float4*)(&Bs[kk][tx * 8 + 4]);
#pragma unroll
            for (int i = 0; i < 8; i++)
#pragma unroll
                for (int j = 0; j < 8; j++)
                    acc[i][j] += a[i] * b[j];
        }
        __syncthreads();
    }

#pragma unroll
    for (int i = 0; i < 8; i++) {
        float4 o0, o1;
        o0.x = acc[i][0] * scale; o0.y = acc[i][1] * scale;
        o0.z = acc[i][2] * scale; o0.w = acc[i][3] * scale;
        o1.x = acc[i][4] * scale; o1.y = acc[i][5] * scale;
        o1.z = acc[i][6] * scale; o1.w = acc[i][7] * scale;
        float* cp = C + (size_t)(rowBase + ty * 8 + i) * N + colBase + tx * 8;
        *(float4*)(cp)     = o0;
        *(float4*)(cp + 4) = o1;
    }
}

__global__ __launch_bounds__(256) void sgemm_proj(
    const float* __restrict__ x, const float* __restrict__ w, int which, float scale)
{
    float* C = (which == 0) ? g_q : (which == 1) ? g_k : g_v;
    sgemm_128x128(x, w, C, scale);
}

__global__ __launch_bounds__(256) void sgemm_out(
    const float* __restrict__ wo, float* __restrict__ out)
{
    sgemm_128x128(g_o, wo, out, 1.0f);
}

// =====================================================================
// Flash attention, causal (raster order), factorized relative bias.
// Tile: 64 queries x 64 keys, DH=128.  256 threads, 1 CTA / (q-tile, b*h).
// =====================================================================
#define PPAD 68
#define VPAD 132
#define ATT_SMEM_FLOATS (128*64 + 128*64 + 64*VPAD + 64*PPAD + 64*3 + 256*2 + 128*2)
#define ATT_SMEM_BYTES  (ATT_SMEM_FLOATS * 4)

__global__ __launch_bounds__(256, 1) void attn_kernel(
    const float* __restrict__ rel_row, const float* __restrict__ rel_col)
{
    extern __shared__ float smf[];
    float* Qt   = smf;               // [128][64] (e-major, transposed)
    float* Kt   = Qt + 128 * 64;     // [128][64]
    float* Vs   = Kt + 128 * 64;     // [64][VPAD]
    float* Ps   = Vs + 64 * VPAD;    // [64][PPAD]
    float* mrow = Ps + 64 * PPAD;    // [64]
    float* lrow = mrow + 64;         // [64]
    float* alph = lrow + 64;         // [64]
    float* redm = alph + 64;         // [4][64]
    float* reds = redm + 256;        // [4][64]
    float* rr   = reds + 256;        // [128]
    float* rc   = rr + 128;          // [128]

    const int tid = threadIdx.x;
    const int qt  = 63 - blockIdx.x;      // largest-first for load balance
    const int bh  = blockIdx.y;
    const int b   = bh >> 2;
    const int h   = bh & 3;

    const float* Qg = g_q + (size_t)b * SS * DD + h * DHH;
    const float* Kg = g_k + (size_t)b * SS * DD + h * DHH;
    const float* Vg = g_v + (size_t)b * SS * DD + h * DHH;
    float*       Og = g_o + (size_t)b * SS * DD + h * DHH;

    if (tid < 128) {
        rr[tid] = rel_row[h * 128 + tid];
        rc[tid] = rel_col[h * 128 + tid];
    }
    if (tid < 64) { mrow[tid] = -1e30f; lrow[tid] = 0.f; }

    // load Q tile transposed: Qt[e][i]
    {
        const int q0 = qt * 64;
#pragma unroll
        for (int it = 0; it < 8; it++) {
            int f = tid + it * 256;          // 0..2047 float4s
            int srow = f >> 5;               // 0..63
            int e4 = (f & 31) << 2;          // 0..124
            float4 v = *(const float4*)(Qg + (size_t)(q0 + srow) * DD + e4);
            Qt[(e4 + 0) * 64 + srow] = v.x;
            Qt[(e4 + 1) * 64 + srow] = v.y;
            Qt[(e4 + 2) * 64 + srow] = v.z;
            Qt[(e4 + 3) * 64 + srow] = v.w;
        }
    }

    const int tx = tid & 15;
    const int ty = tid >> 4;
    float acc[4][8];
#pragma unroll
    for (int i = 0; i < 4; i++)
#pragma unroll
        for (int j = 0; j < 8; j++) acc[i][j] = 0.f;

    for (int kt = 0; kt <= qt; kt++) {
        __syncthreads();   // guards Qt/Kt/Vs/Ps reuse (and initial loads)
        const int k0 = kt * 64;
        // load K (transposed) and V tiles
#pragma unroll
        for (int it = 0; it < 8; it++) {
            int f = tid + it * 256;
            int srow = f >> 5;
            int e4 = (f & 31) << 2;
            float4 kv = *(const float4*)(Kg + (size_t)(k0 + srow) * DD + e4);
            Kt[(e4 + 0) * 64 + srow] = kv.x;
            Kt[(e4 + 1) * 64 + srow] = kv.y;
            Kt[(e4 + 2) * 64 + srow] = kv.z;
            Kt[(e4 + 3) * 64 + srow] = kv.w;
            float4 vv = *(const float4*)(Vg + (size_t)(k0 + srow) * DD + e4);
            *(float4*)(Vs + srow * VPAD + e4) = vv;
        }
        __syncthreads();

        // ---- S = Q K^T (4x4 per thread over 64x64 tile) ----
        float sacc[4][4];
#pragma unroll
        for (int i = 0; i < 4; i++)
#pragma unroll
            for (int j = 0; j < 4; j++) sacc[i][j] = 0.f;
#pragma unroll 8
        for (int e = 0; e < 128; e++) {
            float a[4], bb[4];
            *(float4*)a  = *(const float4*)(Qt + e * 64 + ty * 4);
            *(float4*)bb = *(const float4*)(Kt + e * 64 + tx * 4);
#pragma unroll
            for (int i = 0; i < 4; i++)
#pragma unroll
                for (int j = 0; j < 4; j++)
                    sacc[i][j] += a[i] * bb[j];
        }
        // bias + causal mask, write to Ps
        {
            const int i0 = ty * 4, j0 = tx * 4;
#pragma unroll
            for (int di = 0; di < 4; di++) {
                int qi = qt * 64 + i0 + di;
                int qr = qi >> 6, qc = qi & 63;
#pragma unroll
                for (int dj = 0; dj < 4; dj++) {
                    int kj = k0 + j0 + dj;
                    float bias = rr[63 + (kj >> 6) - qr] + rc[63 + (kj & 63) - qc];
                    float sv = sacc[di][dj] + bias;
                    if (kj > qi) sv += NEGV;
                    Ps[(i0 + di) * PPAD + j0 + dj] = sv;
                }
            }
        }
        __syncthreads();

        // ---- online softmax (4 partial lanes per row) ----
        {
            const int i = tid & 63;
            const int part = tid >> 6;
            const int jb = part << 4;
            float lm = -1e30f;
#pragma unroll
            for (int jj = 0; jj < 16; jj++)
                lm = fmaxf(lm, Ps[i * PPAD + jb + jj]);
            redm[part * 64 + i] = lm;
            __syncthreads();
            float mold = mrow[i];
            float mnew = fmaxf(mold,
                         fmaxf(fmaxf(redm[i], redm[64 + i]),
                               fmaxf(redm[128 + i], redm[192 + i])));
            float ls = 0.f;
#pragma unroll
            for (int jj = 0; jj < 16; jj++) {
                float p = __expf(Ps[i * PPAD + jb + jj] - mnew);
                Ps[i * PPAD + jb + jj] = p;
                ls += p;
            }
            reds[part * 64 + i] = ls;
            __syncthreads();
            if (part == 0) {
                float al = __expf(mold - mnew);
                lrow[i] = lrow[i] * al +
                          (reds[i] + reds[64 + i]) + (reds[128 + i] + reds[192 + i]);
                mrow[i] = mnew;
                alph[i] = al;
            }
            __syncthreads();
        }

        // ---- O = O*alpha + P V  (rows ty*4.., cols tx*8..) ----
        {
            float al[4];
#pragma unroll
            for (int dr = 0; dr < 4; dr++) al[dr] = alph[ty * 4 + dr];
#pragma unroll
            for (int dr = 0; dr < 4; dr++)
#pragma unroll
                for (int dc = 0; dc < 8; dc++) acc[dr][dc] *= al[dr];
#pragma unroll 2
            for (int j = 0; j < 64; j++) {
                float a0 = Ps[(ty * 4 + 0) * PPAD + j];
                float a1 = Ps[(ty * 4 + 1) * PPAD + j];
                float a2 = Ps[(ty * 4 + 2) * PPAD + j];
                float a3 = Ps[(ty * 4 + 3) * PPAD + j];
                float bb[8];
                *(float4*)(bb)     = *(const float4*)(Vs + j * VPAD + tx * 8);
                *(float4*)(bb + 4) = *(const float4*)(Vs + j * VPAD + tx * 8 + 4);
#pragma unroll
                for (int dc = 0; dc < 8; dc++) {
                    acc[0][dc] += a0 * bb[dc];
                    acc[1][dc] += a1 * bb[dc];
                    acc[2][dc] += a2 * bb[dc];
                    acc[3][dc] += a3 * bb[dc];
                }
            }
        }
    }

    // ---- normalize + write O ----
    {
        const int q0 = qt * 64;
#pragma unroll
        for (int dr = 0; dr < 4; dr++) {
            float linv = 1.0f / lrow[ty * 4 + dr];
            int srow = q0 + ty * 4 + dr;
            float4 o0, o1;
            o0.x = acc[dr][0] * linv; o0.y = acc[dr][1] * linv;
            o0.z = acc[dr][2] * linv; o0.w = acc[dr][3] * linv;
            o1.x = acc[dr][4] * linv; o1.y = acc[dr][5] * linv;
            o1.z = acc[dr][6] * linv; o1.w = acc[dr][7] * linv;
            float* op = Og + (size_t)srow * DD + tx * 8;
            *(float4*)(op)     = o0;
            *(float4*)(op + 4) = o1;
        }
    }
}

// =====================================================================
extern "C" void kernel_launch(void* const* d_in, const int* in_sizes, int n_in,
                              void* d_out, int out_size)
{
    const float* x       = (const float*)d_in[0];
    const float* wq      = (const float*)d_in[1];
    const float* wk      = (const float*)d_in[2];
    const float* wv      = (const float*)d_in[3];
    const float* wo      = (const float*)d_in[4];
    const float* rel_row = (const float*)d_in[5];
    const float* rel_col = (const float*)d_in[6];
    float* out = (float*)d_out;

    cudaFuncSetAttribute(attn_kernel,
                         cudaFuncAttributeMaxDynamicSharedMemorySize, ATT_SMEM_BYTES);

    dim3 gProj(DD / 128, MTOT / 128);   // (4, 128)
    const float qscale = 0.08838834764831845f;   // DH^-0.5

    sgemm_proj<<<gProj, 256>>>(x, wq, 0, qscale);
    sgemm_proj<<<gProj, 256>>>(x, wk, 1, 1.0f);
    sgemm_proj<<<gProj, 256>>>(x, wv, 2, 1.0f);

    attn_kernel<<<dim3(64, BB * HH), 256, ATT_SMEM_BYTES>>>(rel_row, rel_col);

    sgemm_out<<<gProj, 256>>>(wo, out);
}